// round 8
// baseline (speedup 1.0000x reference)
#include <cuda_runtime.h>

#define D        128
#define K_EMB    1024
#define BM       64
#define BK       16
#define NTHREADS 256
#define SEPAD    132            // Es row stride in floats (33 float4s)

__device__ float g_enorm[K_EMB];
__device__ float g_partial[512];

// f32x2 packed FMA over the d-axis: both lanes accumulate adjacent-d products.
__device__ __forceinline__ void fma2(unsigned long long& acc,
                                     unsigned long long a, unsigned long long b) {
    asm("fma.rn.f32x2 %0, %1, %2, %0;" : "+l"(acc) : "l"(a), "l"(b));
}
__device__ __forceinline__ float fold2(unsigned long long a, unsigned long long b) {
    float a0, a1, b0, b1;
    asm("mov.b64 {%0,%1}, %2;" : "=f"(a0), "=f"(a1) : "l"(a));
    asm("mov.b64 {%0,%1}, %2;" : "=f"(b0), "=f"(b1) : "l"(b));
    return (a0 + a1) + (b0 + b1);
}

// ---------------- kernel 1: ||e||^2 per embedding ----------------
__global__ void vq_enorm_kernel(const float* __restrict__ emb) {
    int w    = (blockIdx.x * blockDim.x + threadIdx.x) >> 5;
    int lane = threadIdx.x & 31;
    if (w >= K_EMB) return;
    float4 v = ((const float4*)emb)[w * 32 + lane];
    float s = v.x * v.x + v.y * v.y + v.z * v.z + v.w * v.w;
    #pragma unroll
    for (int o = 16; o > 0; o >>= 1) s += __shfl_xor_sync(0xffffffffu, s, o);
    if (lane == 0) g_enorm[w] = s;
}

// ---------------- kernel 2: scores + argmin + gather + loss partial ----------------
__global__ __launch_bounds__(NTHREADS)
void vq_main_kernel(const float* __restrict__ x, const float* __restrict__ emb,
                    float* __restrict__ out) {
    __shared__ __align__(16) float Xs[BM * D];       // 32768 B (row-major)
    __shared__ __align__(16) float Es[BK * SEPAD];   //  8448 B (padded; reused as scratch)
    __shared__ float ens[K_EMB];                     //  4096 B
    __shared__ int   sIdx[BM];
    __shared__ float lossp[8];

    const int t  = threadIdx.x;
    const int tx = t & 7;               // column group: cols {tx, tx+8}
    const int ty = t >> 3;              // row group:    rows {ty, ty+32}
    const int row0 = blockIdx.x * BM;

    #pragma unroll
    for (int i = 0; i < K_EMB / NTHREADS; ++i)
        ens[t + i * NTHREADS] = g_enorm[t + i * NTHREADS];

    // X tile: coalesced float4, row-major (stride 32 float4s)
    {
        const float4* xg = (const float4*)(x + (size_t)row0 * D);
        float4*       xs = (float4*)Xs;
        #pragma unroll
        for (int it = 0; it < BM * D / 4 / NTHREADS; ++it) {
            int flat = t + it * NTHREADS;
            xs[flat] = xg[flat];
        }
    }

    // per-thread bests: 2 row slots (rows ty and ty+32)
    float bestS[2] = {3.4e38f, 3.4e38f};
    int   bestI[2] = {0, 0};

    for (int tile = 0; tile < K_EMB / BK; ++tile) {
        __syncthreads();
        // E tile: 16 codes x 128 floats into padded rows (warp writes one row)
        {
            const float4* eg = (const float4*)(emb + (size_t)tile * BK * D);
            #pragma unroll
            for (int it = 0; it < BK * D / 4 / NTHREADS; ++it) {
                int flat = t + it * NTHREADS;
                int r = flat >> 5, c = flat & 31;
                *(float4*)&Es[r * SEPAD + 4 * c] = eg[r * 32 + c];
            }
        }
        __syncthreads();

        // acc[r][c][p]: r in {ty,ty+32}, c in {tx,tx+8}, p = d-pair parity (d%4<2 vs >=2)
        unsigned long long acc[2][2][2];
        #pragma unroll
        for (int r = 0; r < 2; ++r)
            #pragma unroll
            for (int c = 0; c < 2; ++c) { acc[r][c][0] = 0ull; acc[r][c][1] = 0ull; }

        const ulonglong2* e0p = (const ulonglong2*)&Es[ tx      * SEPAD];
        const ulonglong2* e1p = (const ulonglong2*)&Es[(tx + 8) * SEPAD];
        const ulonglong2* x0p = (const ulonglong2*)&Xs[ ty       * D];
        const ulonglong2* x1p = (const ulonglong2*)&Xs[(ty + 32) * D];

        #pragma unroll 4
        for (int d4 = 0; d4 < D / 4; ++d4) {
            ulonglong2 e0 = e0p[d4];
            ulonglong2 e1 = e1p[d4];
            ulonglong2 xa = x0p[d4];
            ulonglong2 xb = x1p[d4];
            fma2(acc[0][0][0], xa.x, e0.x);  fma2(acc[0][0][1], xa.y, e0.y);
            fma2(acc[0][1][0], xa.x, e1.x);  fma2(acc[0][1][1], xa.y, e1.y);
            fma2(acc[1][0][0], xb.x, e0.x);  fma2(acc[1][0][1], xb.y, e0.y);
            fma2(acc[1][1][0], xb.x, e1.x);  fma2(acc[1][1][1], xb.y, e1.y);
        }

        int kg0 = tile * BK + tx;
        int kg1 = kg0 + 8;
        float h0 = 0.5f * ens[kg0];
        float h1 = 0.5f * ens[kg1];
        #pragma unroll
        for (int r = 0; r < 2; ++r) {
            float s0 = h0 - fold2(acc[r][0][0], acc[r][0][1]);
            float s1 = h1 - fold2(acc[r][1][0], acc[r][1][1]);
            // strict < : earlier (lower) index wins ties; kg0 < kg1 and tiles ascend
            if (s0 < bestS[r]) { bestS[r] = s0; bestI[r] = kg0; }
            if (s1 < bestS[r]) { bestS[r] = s1; bestI[r] = kg1; }
        }
    }

    // ---- cross-thread argmin: 8 candidates per row (overlay Es) ----
    float* sS = Es;                    // [BM*8] floats
    int*   sI = (int*)(Es + BM * 8);   // [BM*8] ints (total 4KB of 8.4KB region)
    __syncthreads();
    #pragma unroll
    for (int r = 0; r < 2; ++r) {
        int row = ty + 32 * r;
        sS[row * 8 + tx] = bestS[r];
        sI[row * 8 + tx] = bestI[r];
    }
    __syncthreads();
    if (t < BM) {
        float bs = sS[t * 8];
        int   bi = sI[t * 8];
        #pragma unroll
        for (int q = 1; q < 8; ++q) {
            float s  = sS[t * 8 + q];
            int   ii = sI[t * 8 + q];
            if (s < bs || (s == bs && ii < bi)) { bs = s; bi = ii; }
        }
        sIdx[t] = bi;
    }
    __syncthreads();

    // ---- q gather (coalesced) + loss partial ----
    int w = t >> 5, lane = t & 31;
    float lsum = 0.f;
    #pragma unroll
    for (int rr = 0; rr < BM / 8; ++rr) {
        int r  = w * (BM / 8) + rr;
        int bi = sIdx[r];
        float4 e4 = ((const float4*)emb)[bi * 32 + lane];
        float4 x4 = *(const float4*)&Xs[r * D + 4 * lane];
        float dx = e4.x - x4.x, dy = e4.y - x4.y, dz = e4.z - x4.z, dw = e4.w - x4.w;
        lsum += dx * dx + dy * dy + dz * dz + dw * dw;
        ((float4*)out)[(size_t)(row0 + r) * 32 + lane] = e4;
    }
    #pragma unroll
    for (int o = 16; o > 0; o >>= 1) lsum += __shfl_xor_sync(0xffffffffu, lsum, o);
    if (lane == 0) lossp[w] = lsum;
    __syncthreads();
    if (t == 0) {
        float s = 0.f;
        #pragma unroll
        for (int w2 = 0; w2 < 8; ++w2) s += lossp[w2];
        g_partial[blockIdx.x] = s;
    }
}

// ---------------- kernel 3: deterministic loss finalize ----------------
__global__ void vq_loss_finalize(float* __restrict__ out, int nblocks, long long pos) {
    __shared__ float s[NTHREADS];
    int t = threadIdx.x;
    float acc = 0.f;
    for (int i = t; i < nblocks; i += NTHREADS) acc += g_partial[i];
    s[t] = acc;
    __syncthreads();
    #pragma unroll
    for (int o = NTHREADS / 2; o > 0; o >>= 1) {
        if (t < o) s[t] += s[t + o];
        __syncthreads();
    }
    if (t == 0) out[pos] = 1.5f * s[0];  // codebook + BETA*commitment = 1.5 * sum((q-x)^2)
}

// ---------------- launch ----------------
extern "C" void kernel_launch(void* const* d_in, const int* in_sizes, int n_in,
                              void* d_out, int out_size) {
    const float* x = (const float*)d_in[0];
    const float* e = (const float*)d_in[1];
    int nx = in_sizes[0];
    if (n_in >= 2 && in_sizes[0] == K_EMB * D && in_sizes[1] != K_EMB * D) {
        const float* tmp = x; x = e; e = tmp;
        nx = in_sizes[1];
    }
    int N = nx / D;                  // 32768
    int nblocks = N / BM;            // 512

    vq_enorm_kernel<<<K_EMB / 8, NTHREADS>>>(e);
    vq_main_kernel<<<nblocks, NTHREADS>>>(x, e, (float*)d_out);
    if (out_size > N * D) {
        vq_loss_finalize<<<1, NTHREADS>>>((float*)d_out, nblocks, (long long)N * D);
    }
}

// round 12
// speedup vs baseline: 5.1026x; 5.1026x over previous
#include <cuda_runtime.h>
#include <cuda_bf16.h>
#include <cstdint>

#define D        128
#define K_EMB    1024
#define BM       64
#define BN       32
#define NCHUNK   (K_EMB / BN)    // 32
#define NTHREADS 256

// dynamic smem (bytes): 256B-row bf16 tiles, XOR-16B swizzle
#define OFF_XH   0
#define OFF_XL   16384
#define OFF_EH   32768
#define OFF_EL   40960
#define SMEM_SZ  49152           // exactly 48KB dynamic, ZERO static: fits default limit

__device__ __nv_bfloat16 g_Eh[K_EMB * D];
__device__ __nv_bfloat16 g_El[K_EMB * D];
__device__ float g_ens[K_EMB];      // 0.5*||e||^2
__device__ float g_partial[512];

// ---------------- helpers ----------------
__device__ __forceinline__ uint32_t smem_u32(const void* p) {
    uint32_t a;
    asm("{ .reg .u64 t; cvta.to.shared.u64 t, %1; cvt.u32.u64 %0, t; }" : "=r"(a) : "l"(p));
    return a;
}
// swizzled byte offset within a 256B-row tile (XOR on 16B units)
__device__ __forceinline__ int sw(int r, int c2) {
    return r * 256 + (c2 ^ ((r & 7) << 4));
}
__device__ __forceinline__ void ldsm4(uint32_t* r, uint32_t addr) {
    asm volatile("ldmatrix.sync.aligned.m8n8.x4.shared.b16 {%0,%1,%2,%3}, [%4];"
                 : "=r"(r[0]), "=r"(r[1]), "=r"(r[2]), "=r"(r[3]) : "r"(addr));
}
__device__ __forceinline__ void mma16816(float* c, const uint32_t* a, uint32_t b0, uint32_t b1) {
    asm volatile(
        "mma.sync.aligned.m16n8k16.row.col.f32.bf16.bf16.f32 "
        "{%0,%1,%2,%3}, {%4,%5,%6,%7}, {%8,%9}, {%0,%1,%2,%3};"
        : "+f"(c[0]), "+f"(c[1]), "+f"(c[2]), "+f"(c[3])
        : "r"(a[0]), "r"(a[1]), "r"(a[2]), "r"(a[3]), "r"(b0), "r"(b1));
}
// split fp32x4 -> bf16 hi (8B) + bf16 lo (8B)
__device__ __forceinline__ void split4(float4 v, uint2& hv, uint2& lv) {
    __nv_bfloat162 h01 = __floats2bfloat162_rn(v.x, v.y);
    __nv_bfloat162 h23 = __floats2bfloat162_rn(v.z, v.w);
    float lx = v.x - __bfloat162float(__low2bfloat16(h01));
    float ly = v.y - __bfloat162float(__high2bfloat16(h01));
    float lz = v.z - __bfloat162float(__low2bfloat16(h23));
    float lw = v.w - __bfloat162float(__high2bfloat16(h23));
    __nv_bfloat162 l01 = __floats2bfloat162_rn(lx, ly);
    __nv_bfloat162 l23 = __floats2bfloat162_rn(lz, lw);
    hv = make_uint2(*(uint32_t*)&h01, *(uint32_t*)&h23);
    lv = make_uint2(*(uint32_t*)&l01, *(uint32_t*)&l23);
}

// ---------------- kernel 1: split emb -> bf16 hi/lo + half-norms ----------------
__global__ void vq_prep(const float* __restrict__ emb) {
    int g = blockIdx.x * blockDim.x + threadIdx.x;
    int w = g >> 5, lane = g & 31;
    if (w >= K_EMB) return;
    float4 v = ((const float4*)emb)[w * 32 + lane];
    float s = v.x * v.x + v.y * v.y + v.z * v.z + v.w * v.w;
    #pragma unroll
    for (int o = 16; o > 0; o >>= 1) s += __shfl_xor_sync(0xffffffffu, s, o);
    if (lane == 0) g_ens[w] = 0.5f * s;
    uint2 hv, lv;
    split4(v, hv, lv);
    ((uint2*)(g_Eh + (size_t)w * D))[lane] = hv;
    ((uint2*)(g_El + (size_t)w * D))[lane] = lv;
}

// ---------------- kernel 2: HMMA scores + argmin + gather + loss ----------------
extern __shared__ char smc[];

__global__ void __launch_bounds__(NTHREADS, 2)
vq_main_kernel(const float* __restrict__ x, const float* __restrict__ emb,
               float* __restrict__ out) {
    const int t = threadIdx.x, wid = t >> 5, lane = t & 31;
    const int rowgrp = wid & 3;        // 4 row groups of 16 rows
    const int colgrp = wid >> 2;       // 2 col groups of 16 cols
    const int row0 = blockIdx.x * BM;
    uint32_t sb = smem_u32(smc);

    // ---- X tile: load fp32, split hi/lo, store swizzled ----
    const float4* xg = (const float4*)(x + (size_t)row0 * D);
    #pragma unroll
    for (int it = 0; it < BM * D / 4 / NTHREADS; ++it) {
        int f = t + it * NTHREADS;
        int r = f >> 5, c4 = f & 31;
        uint2 hv, lv;
        split4(xg[f], hv, lv);
        *(uint2*)(smc + OFF_XH + sw(r, c4 * 8)) = hv;
        *(uint2*)(smc + OFF_XL + sw(r, c4 * 8)) = lv;
    }

    // per-thread fragment address components (constant across k-loop)
    const int rA = rowgrp * 16 + (lane & 15);
    const uint32_t aXh = sb + OFF_XH + rA * 256, aXl = sb + OFF_XL + rA * 256;
    const int xorA = (rA & 7) << 4, koA = (lane & 16) ? 16 : 0;
    const int rB = colgrp * 16 + (lane & 7) + ((lane & 16) >> 1);
    const uint32_t aEh = sb + OFF_EH + rB * 256, aEl = sb + OFF_EL + rB * 256;
    const int xorB = (rB & 7) << 4, koB = (lane & 8) ? 16 : 0;

    float b0S = 3.4e38f, b1S = 3.4e38f;
    int   b0I = 0,       b1I = 0;

    for (int c = 0; c < NCHUNK; ++c) {
        __syncthreads();   // previous chunk compute done (also covers X stores at c=0)
        // ---- E chunk: 32 codes x 128 bf16, hi+lo, swizzled ----
        {
            const uint4* gh = (const uint4*)(g_Eh + (size_t)c * BN * D);
            const uint4* gl = (const uint4*)(g_El + (size_t)c * BN * D);
            #pragma unroll
            for (int it = 0; it < BN * D * 2 / 16 / NTHREADS; ++it) {
                int f = t + it * NTHREADS;
                int r = f >> 4, u = f & 15;
                *(uint4*)(smc + OFF_EH + sw(r, u * 16)) = gh[f];
                *(uint4*)(smc + OFF_EL + sw(r, u * 16)) = gl[f];
            }
        }
        __syncthreads();

        float acc[2][4] = {{0.f,0.f,0.f,0.f},{0.f,0.f,0.f,0.f}};
        #pragma unroll
        for (int ks = 0; ks < D / 16; ++ks) {
            int k2 = ks * 32;
            uint32_t ah[4], al[4], bh[4], bl[4];
            ldsm4(ah, aXh + ((k2 + koA) ^ xorA));
            ldsm4(al, aXl + ((k2 + koA) ^ xorA));
            ldsm4(bh, aEh + ((k2 + koB) ^ xorB));
            ldsm4(bl, aEl + ((k2 + koB) ^ xorB));
            mma16816(acc[0], ah, bh[0], bh[1]);
            mma16816(acc[0], ah, bl[0], bl[1]);
            mma16816(acc[0], al, bh[0], bh[1]);
            mma16816(acc[1], ah, bh[2], bh[3]);
            mma16816(acc[1], ah, bl[2], bl[3]);
            mma16816(acc[1], al, bh[2], bh[3]);
        }

        // ---- fold into running argmin (score = 0.5||e||^2 - x.e) ----
        int nb = c * BN + colgrp * 16;
        #pragma unroll
        for (int f = 0; f < 2; ++f) {
            int col0 = nb + f * 8 + (lane & 3) * 2;
            float e0 = __ldg(&g_ens[col0]);
            float e1 = __ldg(&g_ens[col0 + 1]);
            float s00 = e0 - acc[f][0], s01 = e1 - acc[f][1];
            float s10 = e0 - acc[f][2], s11 = e1 - acc[f][3];
            if (s00 < b0S) { b0S = s00; b0I = col0; }
            if (s01 < b0S) { b0S = s01; b0I = col0 + 1; }
            if (s10 < b1S) { b1S = s10; b1I = col0; }
            if (s11 < b1S) { b1S = s11; b1I = col0 + 1; }
        }
    }

    // ---- quad reduce (lanes sharing C rows: xor over tid bits 0,1) ----
    #pragma unroll
    for (int o = 1; o <= 2; o <<= 1) {
        float oS = __shfl_xor_sync(0xffffffffu, b0S, o);
        int   oI = __shfl_xor_sync(0xffffffffu, b0I, o);
        if (oS < b0S || (oS == b0S && oI < b0I)) { b0S = oS; b0I = oI; }
        oS = __shfl_xor_sync(0xffffffffu, b1S, o);
        oI = __shfl_xor_sync(0xffffffffu, b1I, o);
        if (oS < b1S || (oS == b1S && oI < b1I)) { b1S = oS; b1I = oI; }
    }

    // ---- cross-colgrp merge: overlay scratch into dead E-tile region ----
    float* sS   = (float*)(smc + OFF_EH);          // [BM][2] = 512 B
    int*   sI   = (int*)(smc + OFF_EH + 512);      // [BM][2] = 512 B
    int*   sIdx = (int*)(smc + OFF_EH + 1024);     // [BM]    = 256 B
    float* lossp= (float*)(smc + OFF_EH + 1280);   // [8]
    __syncthreads();   // all ldmatrix reads of E region done before overlay
    if ((lane & 3) == 0) {
        int r0 = rowgrp * 16 + (lane >> 2);
        sS[r0 * 2 + colgrp] = b0S;  sI[r0 * 2 + colgrp] = b0I;
        sS[(r0 + 8) * 2 + colgrp] = b1S;  sI[(r0 + 8) * 2 + colgrp] = b1I;
    }
    __syncthreads();
    if (t < BM) {
        float s0 = sS[2 * t], s1 = sS[2 * t + 1];
        int   i0 = sI[2 * t], i1 = sI[2 * t + 1];
        sIdx[t] = (s1 < s0 || (s1 == s0 && i1 < i0)) ? i1 : i0;
    }
    __syncthreads();

    // ---- q gather (exact fp32) + loss partial ----
    float lsum = 0.f;
    #pragma unroll
    for (int rr = 0; rr < BM / 8; ++rr) {
        int r  = wid * (BM / 8) + rr;
        int bi = sIdx[r];
        float4 e4 = ((const float4*)emb)[bi * 32 + lane];
        float4 x4 = xg[r * 32 + lane];
        float dx = e4.x - x4.x, dy = e4.y - x4.y, dz = e4.z - x4.z, dw = e4.w - x4.w;
        lsum += dx * dx + dy * dy + dz * dz + dw * dw;
        ((float4*)out)[(size_t)(row0 + r) * 32 + lane] = e4;
    }
    #pragma unroll
    for (int o = 16; o > 0; o >>= 1) lsum += __shfl_xor_sync(0xffffffffu, lsum, o);
    if (lane == 0) lossp[wid] = lsum;
    __syncthreads();
    if (t == 0) {
        float s = 0.f;
        #pragma unroll
        for (int w2 = 0; w2 < 8; ++w2) s += lossp[w2];
        g_partial[blockIdx.x] = s;
    }
}

// ---------------- kernel 3: deterministic loss finalize ----------------
__global__ void vq_loss_finalize(float* __restrict__ out, int nblocks, long long pos) {
    __shared__ float s[NTHREADS];
    int t = threadIdx.x;
    float acc = 0.f;
    for (int i = t; i < nblocks; i += NTHREADS) acc += g_partial[i];
    s[t] = acc;
    __syncthreads();
    #pragma unroll
    for (int o = NTHREADS / 2; o > 0; o >>= 1) {
        if (t < o) s[t] += s[t + o];
        __syncthreads();
    }
    if (t == 0) out[pos] = 1.5f * s[0];   // codebook + BETA*commitment = 1.5*sum((q-x)^2)
}

// ---------------- launch ----------------
extern "C" void kernel_launch(void* const* d_in, const int* in_sizes, int n_in,
                              void* d_out, int out_size) {
    const float* x = (const float*)d_in[0];
    const float* e = (const float*)d_in[1];
    int nx = in_sizes[0];
    if (n_in >= 2 && in_sizes[0] == K_EMB * D && in_sizes[1] != K_EMB * D) {
        const float* tmp = x; x = e; e = tmp;
        nx = in_sizes[1];
    }
    int N = nx / D;                   // 32768
    int nblocks = N / BM;             // 512

    vq_prep<<<K_EMB * 32 / NTHREADS, NTHREADS>>>(e);
    vq_main_kernel<<<nblocks, NTHREADS, SMEM_SZ>>>(x, e, (float*)d_out);
    if (out_size > N * D) {
        vq_loss_finalize<<<1, NTHREADS>>>((float*)d_out, nblocks, (long long)N * D);
    }
}

// round 14
// speedup vs baseline: 6.6615x; 1.3055x over previous
#include <cuda_runtime.h>
#include <cuda_bf16.h>
#include <cstdint>

#define D        128
#define K_EMB    1024
#define BM       64
#define BN       32
#define NCHUNK   (K_EMB / BN)    // 32
#define NTHREADS 256

// dynamic smem (bytes)
// phase 1 (X staging): XH@0 (16KB), XL@16384 (16KB)
// phase 2 (E pipeline): buf b at b*16KB: EH@+0 (8KB), EL@+8192 (8KB)
// ens table @32768 (4KB). epilogue scratch overlays @0.
#define EBUF(b)  ((b) * 16384)
#define OFF_XH   0
#define OFF_XL   16384
#define OFF_ENS  32768
#define SMEM_SZ  36864

__device__ __nv_bfloat16 g_Eh[K_EMB * D];
__device__ __nv_bfloat16 g_El[K_EMB * D];
__device__ float g_ens[K_EMB];      // 0.5*||e||^2
__device__ float g_partial[512];

// ---------------- helpers ----------------
__device__ __forceinline__ uint32_t smem_u32(const void* p) {
    uint32_t a;
    asm("{ .reg .u64 t; cvta.to.shared.u64 t, %1; cvt.u32.u64 %0, t; }" : "=r"(a) : "l"(p));
    return a;
}
// swizzled byte offset within a 256B-row tile (XOR 16B units)
__device__ __forceinline__ int sw(int r, int cb) {
    return r * 256 + (cb ^ ((r & 7) << 4));
}
__device__ __forceinline__ void ldsm4(uint32_t* r, uint32_t addr) {
    asm volatile("ldmatrix.sync.aligned.m8n8.x4.shared.b16 {%0,%1,%2,%3}, [%4];"
                 : "=r"(r[0]), "=r"(r[1]), "=r"(r[2]), "=r"(r[3]) : "r"(addr));
}
__device__ __forceinline__ void mma16816(float* c, const uint32_t* a, uint32_t b0, uint32_t b1) {
    asm volatile(
        "mma.sync.aligned.m16n8k16.row.col.f32.bf16.bf16.f32 "
        "{%0,%1,%2,%3}, {%4,%5,%6,%7}, {%8,%9}, {%0,%1,%2,%3};"
        : "+f"(c[0]), "+f"(c[1]), "+f"(c[2]), "+f"(c[3])
        : "r"(a[0]), "r"(a[1]), "r"(a[2]), "r"(a[3]), "r"(b0), "r"(b1));
}
__device__ __forceinline__ void cpasync16(uint32_t dst, const void* src) {
    asm volatile("cp.async.cg.shared.global [%0], [%1], 16;" :: "r"(dst), "l"(src));
}
__device__ __forceinline__ void split4(float4 v, uint2& hv, uint2& lv) {
    __nv_bfloat162 h01 = __floats2bfloat162_rn(v.x, v.y);
    __nv_bfloat162 h23 = __floats2bfloat162_rn(v.z, v.w);
    float lx = v.x - __bfloat162float(__low2bfloat16(h01));
    float ly = v.y - __bfloat162float(__high2bfloat16(h01));
    float lz = v.z - __bfloat162float(__low2bfloat16(h23));
    float lw = v.w - __bfloat162float(__high2bfloat16(h23));
    __nv_bfloat162 l01 = __floats2bfloat162_rn(lx, ly);
    __nv_bfloat162 l23 = __floats2bfloat162_rn(lz, lw);
    hv = make_uint2(*(uint32_t*)&h01, *(uint32_t*)&h23);
    lv = make_uint2(*(uint32_t*)&l01, *(uint32_t*)&l23);
}

// ---------------- kernel 1: split emb -> bf16 hi/lo + half-norms ----------------
__global__ void vq_prep(const float* __restrict__ emb) {
    int g = blockIdx.x * blockDim.x + threadIdx.x;
    int w = g >> 5, lane = g & 31;
    if (w >= K_EMB) return;
    float4 v = ((const float4*)emb)[w * 32 + lane];
    float s = v.x * v.x + v.y * v.y + v.z * v.z + v.w * v.w;
    #pragma unroll
    for (int o = 16; o > 0; o >>= 1) s += __shfl_xor_sync(0xffffffffu, s, o);
    if (lane == 0) g_ens[w] = 0.5f * s;
    uint2 hv, lv;
    split4(v, hv, lv);
    ((uint2*)(g_Eh + (size_t)w * D))[lane] = hv;
    ((uint2*)(g_El + (size_t)w * D))[lane] = lv;
}

// ---------------- kernel 2: pipelined HMMA scores + argmin + gather + loss ----------------
extern __shared__ char smc[];

__global__ void __launch_bounds__(NTHREADS, 2)
vq_main_kernel(const float* __restrict__ x, const float* __restrict__ emb,
               float* __restrict__ out) {
    const int t = threadIdx.x, wid = t >> 5, lane = t & 31;
    const int rowgrp = wid & 3;        // 4 row groups of 16 rows
    const int colgrp = wid >> 2;       // 2 col groups of 16 cols
    const int row0 = blockIdx.x * BM;
    uint32_t sb = smem_u32(smc);
    float* ens = (float*)(smc + OFF_ENS);

    #pragma unroll
    for (int i = 0; i < K_EMB / NTHREADS; ++i)
        ens[t + i * NTHREADS] = g_ens[t + i * NTHREADS];

    // ---- phase 1: X tile -> smem (split hi/lo, swizzled) ----
    const float4* xg = (const float4*)(x + (size_t)row0 * D);
    #pragma unroll
    for (int it = 0; it < BM * D / 4 / NTHREADS; ++it) {
        int f = t + it * NTHREADS;
        int r = f >> 5, c4 = f & 31;
        uint2 hv, lv;
        split4(xg[f], hv, lv);
        *(uint2*)(smc + OFF_XH + sw(r, c4 * 8)) = hv;
        *(uint2*)(smc + OFF_XL + sw(r, c4 * 8)) = lv;
    }
    __syncthreads();

    // ---- hoist A fragments into registers (once) ----
    const int rA = rowgrp * 16 + (lane & 15);
    const uint32_t aXh = sb + OFF_XH + rA * 256, aXl = sb + OFF_XL + rA * 256;
    const int xorA = (rA & 7) << 4, koA = (lane & 16) ? 16 : 0;
    uint32_t ah[8][4], al[8][4];
    #pragma unroll
    for (int ks = 0; ks < 8; ++ks) {
        ldsm4(ah[ks], aXh + ((ks * 32 + koA) ^ xorA));
        ldsm4(al[ks], aXl + ((ks * 32 + koA) ^ xorA));
    }
    __syncthreads();   // X region now dead -> becomes E double buffer

    // E fragment addressing
    const int rB = colgrp * 16 + (lane & 7) + ((lane & 16) >> 1);
    const int xorB = (rB & 7) << 4, koB = (lane & 8) ? 16 : 0;
    const uint32_t ebR = rB * 256;

    auto prefetch = [&](int c, uint32_t bufoff) {
        const char* gh = (const char*)(g_Eh + (size_t)c * BN * D);
        const char* gl = (const char*)(g_El + (size_t)c * BN * D);
        #pragma unroll
        for (int it = 0; it < 2; ++it) {
            int f = t + it * NTHREADS;          // 0..511 (16B units)
            int r = f >> 4, u = (f & 15) * 16;
            cpasync16(sb + bufoff + sw(r, u), gh + f * 16);
            cpasync16(sb + bufoff + 8192 + sw(r, u), gl + f * 16);
        }
    };
    prefetch(0, EBUF(0));
    asm volatile("cp.async.commit_group;");
    prefetch(1, EBUF(1));
    asm volatile("cp.async.commit_group;");

    float b0S = 3.4e38f, b1S = 3.4e38f;
    int   b0I = 0,       b1I = 0;

    for (int c = 0; c < NCHUNK; ++c) {
        asm volatile("cp.async.wait_group 1;");
        __syncthreads();                         // buf[c&1] ready for all warps
        const uint32_t eb = sb + EBUF(c & 1);

        float hcc[2][4] = {{0.f,0.f,0.f,0.f},{0.f,0.f,0.f,0.f}};   // hi*hi
        float ccc[2][4] = {{0.f,0.f,0.f,0.f},{0.f,0.f,0.f,0.f}};   // corrections
        #pragma unroll
        for (int ks = 0; ks < 8; ++ks) {
            uint32_t bh[4], bl[4];
            ldsm4(bh, eb + ebR + ((ks * 32 + koB) ^ xorB));
            ldsm4(bl, eb + 8192 + ebR + ((ks * 32 + koB) ^ xorB));
            mma16816(hcc[0], ah[ks], bh[0], bh[1]);
            mma16816(ccc[0], ah[ks], bl[0], bl[1]);
            mma16816(ccc[0], al[ks], bh[0], bh[1]);
            mma16816(hcc[1], ah[ks], bh[2], bh[3]);
            mma16816(ccc[1], ah[ks], bl[2], bl[3]);
            mma16816(ccc[1], al[ks], bh[2], bh[3]);
        }
        __syncthreads();                         // all warps done reading buf[c&1]
        if (c + 2 < NCHUNK) {
            prefetch(c + 2, EBUF(c & 1));
            asm volatile("cp.async.commit_group;");
        }

        // ---- fold into running argmin (score = 0.5||e||^2 - x.e) ----
        int nb = c * BN + colgrp * 16;
        #pragma unroll
        for (int f = 0; f < 2; ++f) {
            int col0 = nb + f * 8 + (lane & 3) * 2;
            float e0 = ens[col0], e1 = ens[col0 + 1];
            float s00 = e0 - (hcc[f][0] + ccc[f][0]);
            float s01 = e1 - (hcc[f][1] + ccc[f][1]);
            float s10 = e0 - (hcc[f][2] + ccc[f][2]);
            float s11 = e1 - (hcc[f][3] + ccc[f][3]);
            if (s00 < b0S) { b0S = s00; b0I = col0; }
            if (s01 < b0S) { b0S = s01; b0I = col0 + 1; }
            if (s10 < b1S) { b1S = s10; b1I = col0; }
            if (s11 < b1S) { b1S = s11; b1I = col0 + 1; }
        }
    }

    // ---- quad reduce (lanes sharing C rows: xor over tid bits 0,1) ----
    #pragma unroll
    for (int o = 1; o <= 2; o <<= 1) {
        float oS = __shfl_xor_sync(0xffffffffu, b0S, o);
        int   oI = __shfl_xor_sync(0xffffffffu, b0I, o);
        if (oS < b0S || (oS == b0S && oI < b0I)) { b0S = oS; b0I = oI; }
        oS = __shfl_xor_sync(0xffffffffu, b1S, o);
        oI = __shfl_xor_sync(0xffffffffu, b1I, o);
        if (oS < b1S || (oS == b1S && oI < b1I)) { b1S = oS; b1I = oI; }
    }

    // ---- cross-colgrp merge (overlay dead buffer region) ----
    float* sS   = (float*)(smc);              // [BM][2]
    int*   sI   = (int*)(smc + 512);          // [BM][2]
    int*   sIdx = (int*)(smc + 1024);         // [BM]
    float* lossp= (float*)(smc + 1280);       // [8]
    if ((lane & 3) == 0) {
        int r0 = rowgrp * 16 + (lane >> 2);
        sS[r0 * 2 + colgrp] = b0S;  sI[r0 * 2 + colgrp] = b0I;
        sS[(r0 + 8) * 2 + colgrp] = b1S;  sI[(r0 + 8) * 2 + colgrp] = b1I;
    }
    __syncthreads();
    if (t < BM) {
        float s0 = sS[2 * t], s1 = sS[2 * t + 1];
        int   i0 = sI[2 * t], i1 = sI[2 * t + 1];
        sIdx[t] = (s1 < s0 || (s1 == s0 && i1 < i0)) ? i1 : i0;
    }
    __syncthreads();

    // ---- q gather (exact fp32) + loss partial ----
    float lsum = 0.f;
    #pragma unroll
    for (int rr = 0; rr < BM / 8; ++rr) {
        int r  = wid * (BM / 8) + rr;
        int bi = sIdx[r];
        float4 e4 = ((const float4*)emb)[bi * 32 + lane];
        float4 x4 = xg[r * 32 + lane];
        float dx = e4.x - x4.x, dy = e4.y - x4.y, dz = e4.z - x4.z, dw = e4.w - x4.w;
        lsum += dx * dx + dy * dy + dz * dz + dw * dw;
        ((float4*)out)[(size_t)(row0 + r) * 32 + lane] = e4;
    }
    #pragma unroll
    for (int o = 16; o > 0; o >>= 1) lsum += __shfl_xor_sync(0xffffffffu, lsum, o);
    if (lane == 0) lossp[wid] = lsum;
    __syncthreads();
    if (t == 0) {
        float s = 0.f;
        #pragma unroll
        for (int w2 = 0; w2 < 8; ++w2) s += lossp[w2];
        g_partial[blockIdx.x] = s;
    }
}

// ---------------- kernel 3: deterministic loss finalize ----------------
__global__ void vq_loss_finalize(float* __restrict__ out, int nblocks, long long pos) {
    __shared__ float s[NTHREADS];
    int t = threadIdx.x;
    float acc = 0.f;
    for (int i = t; i < nblocks; i += NTHREADS) acc += g_partial[i];
    s[t] = acc;
    __syncthreads();
    #pragma unroll
    for (int o = NTHREADS / 2; o > 0; o >>= 1) {
        if (t < o) s[t] += s[t + o];
        __syncthreads();
    }
    if (t == 0) out[pos] = 1.5f * s[0];   // codebook + BETA*commitment = 1.5*sum((q-x)^2)
}

// ---------------- launch ----------------
extern "C" void kernel_launch(void* const* d_in, const int* in_sizes, int n_in,
                              void* d_out, int out_size) {
    const float* x = (const float*)d_in[0];
    const float* e = (const float*)d_in[1];
    int nx = in_sizes[0];
    if (n_in >= 2 && in_sizes[0] == K_EMB * D && in_sizes[1] != K_EMB * D) {
        const float* tmp = x; x = e; e = tmp;
        nx = in_sizes[1];
    }
    int N = nx / D;                   // 32768
    int nblocks = N / BM;             // 512

    vq_prep<<<K_EMB * 32 / NTHREADS, NTHREADS>>>(e);
    vq_main_kernel<<<nblocks, NTHREADS, SMEM_SZ>>>(x, e, (float*)d_out);
    if (out_size > N * D) {
        vq_loss_finalize<<<1, NTHREADS>>>((float*)d_out, nblocks, (long long)N * D);
    }
}